// round 14
// baseline (speedup 1.0000x reference)
#include <cuda_runtime.h>
#include <cuda_bf16.h>

// Problem constants (fixed by the reference: B=2048, C=16, H=32, W=32 -> F=16384)
#define B_SAMPLES 2048
#define F_FEATS   16384
#define THREADS   128   // 16 CTAs/SM -> whole 2048-CTA grid resident in ONE wave

// Scratch (no device allocation allowed).
__device__ float        g_per_sample[B_SAMPLES];
__device__ unsigned int g_arrive_count = 0;   // reset by the last block each run

__global__ __launch_bounds__(THREADS, 16)   // force regs<=32, 64 warps/SM max
void fnmse_fused_kernel(const float* __restrict__ out,
                        const float* __restrict__ tgt,
                        const float* __restrict__ fw,
                        float* __restrict__ d_out)
{
    const int b   = blockIdx.x;
    const int tid = threadIdx.x;

    const float4* __restrict__ o4 = reinterpret_cast<const float4*>(out + (size_t)b * F_FEATS);
    const float4* __restrict__ t4 = reinterpret_cast<const float4*>(tgt + (size_t)b * F_FEATS);
    const float4* __restrict__ w4 = reinterpret_cast<const float4*>(fw);

    float ssq = 0.0f;
    float cnt = 0.0f;

    // One full row per CTA: 4096 float4 / 128 threads = 32 fully unrolled
    // iterations -> 96 LDG.128s of per-warp pipeline depth (2x R10).
    // .cg for streaming o/t (L2-only), .ca for the L1-resident fw vector.
#pragma unroll
    for (int it = 0; it < (F_FEATS / 4) / THREADS; ++it) {
        const int i = it * THREADS + tid;
        float4 o = __ldcg(&o4[i]);
        float4 t = __ldcg(&t4[i]);
        float4 w = __ldca(&w4[i]);

        {
            bool  m = (t.x == t.x);          // !isnan
            float r = m ? (t.x - o.x) : 0.0f;
            float s = r * w.x;
            ssq = fmaf(s, s, ssq);
            cnt += m ? 1.0f : 0.0f;
        }
        {
            bool  m = (t.y == t.y);
            float r = m ? (t.y - o.y) : 0.0f;
            float s = r * w.y;
            ssq = fmaf(s, s, ssq);
            cnt += m ? 1.0f : 0.0f;
        }
        {
            bool  m = (t.z == t.z);
            float r = m ? (t.z - o.z) : 0.0f;
            float s = r * w.z;
            ssq = fmaf(s, s, ssq);
            cnt += m ? 1.0f : 0.0f;
        }
        {
            bool  m = (t.w == t.w);
            float r = m ? (t.w - o.w) : 0.0f;
            float s = r * w.w;
            ssq = fmaf(s, s, ssq);
            cnt += m ? 1.0f : 0.0f;
        }
    }

    // Warp reduction
#pragma unroll
    for (int off = 16; off > 0; off >>= 1) {
        ssq += __shfl_down_sync(0xFFFFFFFFu, ssq, off);
        cnt += __shfl_down_sync(0xFFFFFFFFu, cnt, off);
    }

    __shared__ float s_ssq[THREADS / 32];
    __shared__ float s_cnt[THREADS / 32];
    const int lane = tid & 31;
    const int wid  = tid >> 5;
    if (lane == 0) { s_ssq[wid] = ssq; s_cnt[wid] = cnt; }
    __syncthreads();

    // Warps 1..3 retire immediately — no fence, no trailing barrier.
    if (wid != 0) return;

    float vs = (lane < THREADS / 32) ? s_ssq[lane] : 0.0f;
    float vc = (lane < THREADS / 32) ? s_cnt[lane] : 0.0f;
#pragma unroll
    for (int off = 2; off > 0; off >>= 1) {
        vs += __shfl_down_sync(0xFFFFFFFFu, vs, off);
        vc += __shfl_down_sync(0xFFFFFFFFu, vc, off);
    }

    int is_last = 0;
    if (lane == 0) {
        // Deposit the per-sample value, then release-arrive (orders the STG;
        // acq_rel gives the last block acquire semantics for the readback).
        g_per_sample[b] = vs / vc;
        unsigned int prev;
        asm volatile("atom.add.acq_rel.gpu.global.u32 %0, [%1], 1;"
                     : "=r"(prev) : "l"(&g_arrive_count) : "memory");
        is_last = (prev == (unsigned int)(gridDim.x - 1));
    }
    is_last = __shfl_sync(0xFFFFFFFFu, is_last, 0);

    // Last-arriving block: warp 0 alone, fixed-order deterministic combine
    // (8KB, L2-resident, 16 float4 loads per lane).
    if (is_last) {
        const float4* p4 = reinterpret_cast<const float4*>(g_per_sample);
        float s = 0.0f;
#pragma unroll
        for (int r = 0; r < B_SAMPLES / 4 / 32; ++r) {
            float4 a = p4[r * 32 + lane];
            s += (a.x + a.y) + (a.z + a.w);
        }
#pragma unroll
        for (int off = 16; off > 0; off >>= 1)
            s += __shfl_down_sync(0xFFFFFFFFu, s, off);
        if (lane == 0) {
            d_out[0] = s;
            g_arrive_count = 0u;   // reset for next graph replay
        }
    }
}

extern "C" void kernel_launch(void* const* d_in, const int* in_sizes, int n_in,
                              void* d_out, int out_size)
{
    // metadata order: output, target, e_exp, sample_weight, feature_weight
    const float* out = (const float*)d_in[0];
    const float* tgt = (const float*)d_in[1];
    // d_in[2] (e_exp) and d_in[3] (sample_weight) are unused by the reference.
    const float* fw  = (const float*)d_in[4];

    fnmse_fused_kernel<<<B_SAMPLES, THREADS>>>(out, tgt, fw, (float*)d_out);
}

// round 15
// speedup vs baseline: 1.0549x; 1.0549x over previous
#include <cuda_runtime.h>
#include <cuda_bf16.h>

// FeatureNormalizedMSE — final converged kernel.
// Problem constants (fixed by the reference: B=2048, C=16, H=32, W=32 -> F=16384)
#define B_SAMPLES 2048
#define F_FEATS   16384
#define THREADS   256

// Session conclusion (14 rounds of ncu-driven search):
//   * 2048 CTAs x 256 threads, 16 fully-unrolled LDG.128 iterations, regs<=32
//     is the unique optimum; every other grid/CTA/unroll/path variant
//     (4096-CTA splits, 128/512-thread CTAs, .cs, cp.async.bulk, single-wave,
//     higher-reg builds) regressed 5-55%.
//   * .cg on the streaming o/t reads + .ca on the L1-resident fw vector gave
//     the best measured kernel durations (45.06-45.41us, ~6.04 TB/s).
//   * Arrival protocol is performance-neutral; acq_rel + last-block combine
//     keeps it single-launch and bitwise deterministic.

// Scratch (no device allocation allowed).
__device__ float        g_per_sample[B_SAMPLES];
__device__ unsigned int g_arrive_count = 0;   // reset by the last block each run

__global__ __launch_bounds__(THREADS, 8)   // pins regs<=32 -> 64 warps/SM
void fnmse_fused_kernel(const float* __restrict__ out,
                        const float* __restrict__ tgt,
                        const float* __restrict__ fw,
                        float* __restrict__ d_out)
{
    const int b   = blockIdx.x;
    const int tid = threadIdx.x;

    const float4* __restrict__ o4 = reinterpret_cast<const float4*>(out + (size_t)b * F_FEATS);
    const float4* __restrict__ t4 = reinterpret_cast<const float4*>(tgt + (size_t)b * F_FEATS);
    const float4* __restrict__ w4 = reinterpret_cast<const float4*>(fw);

    float ssq = 0.0f;
    float cnt = 0.0f;

#pragma unroll
    for (int it = 0; it < (F_FEATS / 4) / THREADS; ++it) {
        const int i = it * THREADS + tid;
        float4 o = __ldcg(&o4[i]);   // streaming: L2-only, keep L1 for fw
        float4 t = __ldcg(&t4[i]);
        float4 w = __ldca(&w4[i]);   // 64KB vector, L1-resident per SM

        {
            bool  m = (t.x == t.x);          // !isnan
            float r = m ? (t.x - o.x) : 0.0f;
            float s = r * w.x;
            ssq = fmaf(s, s, ssq);
            cnt += m ? 1.0f : 0.0f;
        }
        {
            bool  m = (t.y == t.y);
            float r = m ? (t.y - o.y) : 0.0f;
            float s = r * w.y;
            ssq = fmaf(s, s, ssq);
            cnt += m ? 1.0f : 0.0f;
        }
        {
            bool  m = (t.z == t.z);
            float r = m ? (t.z - o.z) : 0.0f;
            float s = r * w.z;
            ssq = fmaf(s, s, ssq);
            cnt += m ? 1.0f : 0.0f;
        }
        {
            bool  m = (t.w == t.w);
            float r = m ? (t.w - o.w) : 0.0f;
            float s = r * w.w;
            ssq = fmaf(s, s, ssq);
            cnt += m ? 1.0f : 0.0f;
        }
    }

    // Warp reduction
#pragma unroll
    for (int off = 16; off > 0; off >>= 1) {
        ssq += __shfl_down_sync(0xFFFFFFFFu, ssq, off);
        cnt += __shfl_down_sync(0xFFFFFFFFu, cnt, off);
    }

    __shared__ float s_ssq[THREADS / 32];
    __shared__ float s_cnt[THREADS / 32];
    const int lane = tid & 31;
    const int wid  = tid >> 5;
    if (lane == 0) { s_ssq[wid] = ssq; s_cnt[wid] = cnt; }
    __syncthreads();

    // Warps 1..7 retire immediately — no fence, no trailing barrier.
    if (wid != 0) return;

    float vs = (lane < THREADS / 32) ? s_ssq[lane] : 0.0f;
    float vc = (lane < THREADS / 32) ? s_cnt[lane] : 0.0f;
#pragma unroll
    for (int off = 4; off > 0; off >>= 1) {
        vs += __shfl_down_sync(0xFFFFFFFFu, vs, off);
        vc += __shfl_down_sync(0xFFFFFFFFu, vc, off);
    }

    int is_last = 0;
    if (lane == 0) {
        // Deposit the per-sample value, then release-arrive (the release orders
        // the STG; acq_rel gives the last block acquire for the readback).
        g_per_sample[b] = vs / vc;
        unsigned int prev;
        asm volatile("atom.add.acq_rel.gpu.global.u32 %0, [%1], 1;"
                     : "=r"(prev) : "l"(&g_arrive_count) : "memory");
        is_last = (prev == (unsigned int)(gridDim.x - 1));
    }
    is_last = __shfl_sync(0xFFFFFFFFu, is_last, 0);

    // Last-arriving block: warp 0 alone, fixed-order deterministic combine
    // (8KB, L2-resident, 16 float4 loads per lane).
    if (is_last) {
        const float4* p4 = reinterpret_cast<const float4*>(g_per_sample);
        float s = 0.0f;
#pragma unroll
        for (int r = 0; r < B_SAMPLES / 4 / 32; ++r) {
            float4 a = p4[r * 32 + lane];
            s += (a.x + a.y) + (a.z + a.w);
        }
#pragma unroll
        for (int off = 16; off > 0; off >>= 1)
            s += __shfl_down_sync(0xFFFFFFFFu, s, off);
        if (lane == 0) {
            d_out[0] = s;
            g_arrive_count = 0u;   // reset for next graph replay
        }
    }
}

extern "C" void kernel_launch(void* const* d_in, const int* in_sizes, int n_in,
                              void* d_out, int out_size)
{
    // metadata order: output, target, e_exp, sample_weight, feature_weight
    const float* out = (const float*)d_in[0];
    const float* tgt = (const float*)d_in[1];
    // d_in[2] (e_exp) and d_in[3] (sample_weight) are unused by the reference.
    const float* fw  = (const float*)d_in[4];

    fnmse_fused_kernel<<<B_SAMPLES, THREADS>>>(out, tgt, fw, (float*)d_out);
}

// round 16
// speedup vs baseline: 1.0794x; 1.0232x over previous
#include <cuda_runtime.h>
#include <cuda_bf16.h>

// FeatureNormalizedMSE — FINAL kernel (converged, round 15).
// Problem constants (fixed by the reference: B=2048, C=16, H=32, W=32 -> F=16384)
#define B_SAMPLES 2048
#define F_FEATS   16384
#define THREADS   256

// Converged configuration after a 15-round ncu-driven search:
//   * 2048 CTAs x 256 threads, one row per CTA, 16 fully-unrolled LDG.128
//     iterations, regs pinned <=32 (64 warps/SM). Unique optimum: all tested
//     alternatives (4096-CTA row splits, 128-thread CTAs, single-wave grids,
//     .cs streaming, cp.async.bulk/TMA, 36-40-reg builds) regressed 5-55%.
//   * .cg on streaming o/t (L2-only, preserves L1 for fw) + .ca on the 64KB
//     feature-weight vector: best measured kernel durations
//     (44.96-45.41us, ~6.05 TB/s — LDG-path demand equilibrium on sm_103a).
//   * Single launch; deterministic: per-sample values deposited in fixed
//     order, acq_rel arrival counter, last block combines in fixed order.

// Scratch (no device allocation allowed).
__device__ float        g_per_sample[B_SAMPLES];
__device__ unsigned int g_arrive_count = 0;   // reset by the last block each run

__global__ __launch_bounds__(THREADS, 8)   // pins regs<=32 -> 64 warps/SM
void fnmse_fused_kernel(const float* __restrict__ out,
                        const float* __restrict__ tgt,
                        const float* __restrict__ fw,
                        float* __restrict__ d_out)
{
    const int b   = blockIdx.x;
    const int tid = threadIdx.x;

    const float4* __restrict__ o4 = reinterpret_cast<const float4*>(out + (size_t)b * F_FEATS);
    const float4* __restrict__ t4 = reinterpret_cast<const float4*>(tgt + (size_t)b * F_FEATS);
    const float4* __restrict__ w4 = reinterpret_cast<const float4*>(fw);

    float ssq = 0.0f;
    float cnt = 0.0f;

#pragma unroll
    for (int it = 0; it < (F_FEATS / 4) / THREADS; ++it) {
        const int i = it * THREADS + tid;
        float4 o = __ldcg(&o4[i]);   // streaming: L2-only, keep L1 for fw
        float4 t = __ldcg(&t4[i]);
        float4 w = __ldca(&w4[i]);   // 64KB vector, L1-resident per SM

        {
            bool  m = (t.x == t.x);          // !isnan
            float r = m ? (t.x - o.x) : 0.0f;
            float s = r * w.x;
            ssq = fmaf(s, s, ssq);
            cnt += m ? 1.0f : 0.0f;
        }
        {
            bool  m = (t.y == t.y);
            float r = m ? (t.y - o.y) : 0.0f;
            float s = r * w.y;
            ssq = fmaf(s, s, ssq);
            cnt += m ? 1.0f : 0.0f;
        }
        {
            bool  m = (t.z == t.z);
            float r = m ? (t.z - o.z) : 0.0f;
            float s = r * w.z;
            ssq = fmaf(s, s, ssq);
            cnt += m ? 1.0f : 0.0f;
        }
        {
            bool  m = (t.w == t.w);
            float r = m ? (t.w - o.w) : 0.0f;
            float s = r * w.w;
            ssq = fmaf(s, s, ssq);
            cnt += m ? 1.0f : 0.0f;
        }
    }

    // Warp reduction
#pragma unroll
    for (int off = 16; off > 0; off >>= 1) {
        ssq += __shfl_down_sync(0xFFFFFFFFu, ssq, off);
        cnt += __shfl_down_sync(0xFFFFFFFFu, cnt, off);
    }

    __shared__ float s_ssq[THREADS / 32];
    __shared__ float s_cnt[THREADS / 32];
    const int lane = tid & 31;
    const int wid  = tid >> 5;
    if (lane == 0) { s_ssq[wid] = ssq; s_cnt[wid] = cnt; }
    __syncthreads();

    // Warps 1..7 retire immediately — no fence, no trailing barrier.
    if (wid != 0) return;

    float vs = (lane < THREADS / 32) ? s_ssq[lane] : 0.0f;
    float vc = (lane < THREADS / 32) ? s_cnt[lane] : 0.0f;
#pragma unroll
    for (int off = 4; off > 0; off >>= 1) {
        vs += __shfl_down_sync(0xFFFFFFFFu, vs, off);
        vc += __shfl_down_sync(0xFFFFFFFFu, vc, off);
    }

    int is_last = 0;
    if (lane == 0) {
        // Deposit the per-sample value, then release-arrive (the release orders
        // the STG; acq_rel gives the last block acquire for the readback).
        g_per_sample[b] = vs / vc;
        unsigned int prev;
        asm volatile("atom.add.acq_rel.gpu.global.u32 %0, [%1], 1;"
                     : "=r"(prev) : "l"(&g_arrive_count) : "memory");
        is_last = (prev == (unsigned int)(gridDim.x - 1));
    }
    is_last = __shfl_sync(0xFFFFFFFFu, is_last, 0);

    // Last-arriving block: warp 0 alone, fixed-order deterministic combine
    // (8KB, L2-resident, 16 float4 loads per lane).
    if (is_last) {
        const float4* p4 = reinterpret_cast<const float4*>(g_per_sample);
        float s = 0.0f;
#pragma unroll
        for (int r = 0; r < B_SAMPLES / 4 / 32; ++r) {
            float4 a = p4[r * 32 + lane];
            s += (a.x + a.y) + (a.z + a.w);
        }
#pragma unroll
        for (int off = 16; off > 0; off >>= 1)
            s += __shfl_down_sync(0xFFFFFFFFu, s, off);
        if (lane == 0) {
            d_out[0] = s;
            g_arrive_count = 0u;   // reset for next graph replay
        }
    }
}

extern "C" void kernel_launch(void* const* d_in, const int* in_sizes, int n_in,
                              void* d_out, int out_size)
{
    // metadata order: output, target, e_exp, sample_weight, feature_weight
    const float* out = (const float*)d_in[0];
    const float* tgt = (const float*)d_in[1];
    // d_in[2] (e_exp) and d_in[3] (sample_weight) are unused by the reference.
    const float* fw  = (const float*)d_in[4];

    fnmse_fused_kernel<<<B_SAMPLES, THREADS>>>(out, tgt, fw, (float*)d_out);
}